// round 13
// baseline (speedup 1.0000x reference)
#include <cuda_runtime.h>

// Problem constants (fixed by setup_inputs)
#define B_     8
#define N_     3072
#define D_     1024
#define D4_    256          // D/4 (float4)
#define STEPS  1024         // N/POOL
#define POOL_  3
#define NCH    64           // chunks per batch
#define CWIN   16           // windows per chunk
#define EPS_   0.006f

// Scratch (__device__ globals; no allocations allowed)
__device__ float g_L [(size_t)B_ * (STEPS + 1) * D_];  // chunk-local exclusive window prefix
__device__ float g_S [(size_t)B_ * NCH * D_];          // chunk totals
__device__ float g_SP[(size_t)B_ * (NCH + 1) * D_];    // exclusive scan of chunk totals
__device__ int   g_is32;                               // 1 if graph is int32

__device__ __forceinline__ float4 f4add(float4 a, float4 b) {
    return make_float4(a.x + b.x, a.y + b.y, a.z + b.z, a.w + b.w);
}
__device__ __forceinline__ float4 f4sub(float4 a, float4 b) {
    return make_float4(a.x - b.x, a.y - b.y, a.z - b.z, a.w - b.w);
}
__device__ __forceinline__ float4 ldcs4(const float4* p) { return __ldcs(p); }
__device__ __forceinline__ void stcs4(float4* p, float4 v) { __stcs(p, v); }

// ---------------------------------------------------------------------------
// 1) Fused pass over x (streamed), depth-2 register pipeline. Writes ONLY the
//    chunk-local exclusive prefix L (L2-resident) and chunk totals S — the
//    window-mean output rows are reconstructed by k_gather from the prefix,
//    halving this kernel's store traffic. Block 0 also does dtype detection.
// ---------------------------------------------------------------------------
__global__ void __launch_bounds__(256) k_fused(const float4* __restrict__ x,
                                               const unsigned int* __restrict__ g32,
                                               float4* __restrict__ out) {
    __shared__ unsigned int sh[256];
    int blk = blockIdx.x;               // B*NCH = 512 blocks
    int b = blk >> 6, c = blk & 63;
    int q0 = c * CWIN;
    int i = threadIdx.x;

    const float4* xr = x + ((size_t)(b * N_ + POOL_ * q0)) * D4_ + i;
    float4* L4 = (float4*)g_L + ((size_t)b * (STEPS + 1) + q0) * D4_ + i;

    float4 run = make_float4(0.f, 0.f, 0.f, 0.f);

    // pipeline prologue: windows 0 and 1 in flight
    float4 A0 = ldcs4(&xr[0]);
    float4 B0 = ldcs4(&xr[(size_t)1 * D4_]);
    float4 C0 = ldcs4(&xr[(size_t)2 * D4_]);
    float4 A1 = ldcs4(&xr[(size_t)3 * D4_]);
    float4 B1 = ldcs4(&xr[(size_t)4 * D4_]);
    float4 C1 = ldcs4(&xr[(size_t)5 * D4_]);

#pragma unroll
    for (int w = 0; w < CWIN; w++) {
        float4 A2, B2, C2;
        if (w + 2 < CWIN) {                  // prefetch window w+2
            A2 = ldcs4(&xr[(size_t)(3 * (w + 2))     * D4_]);
            B2 = ldcs4(&xr[(size_t)(3 * (w + 2) + 1) * D4_]);
            C2 = ldcs4(&xr[(size_t)(3 * (w + 2) + 2) * D4_]);
        }
        L4[(size_t)w * D4_] = run;                       // keep in L2
        float4 sum = f4add(f4add(A0, B0), C0);           // raw row-sum
        run = f4add(run, sum);
        A0 = A1; B0 = B1; C0 = C1;
        A1 = A2; B1 = B2; C1 = C2;
    }
    ((float4*)g_S)[((size_t)b * NCH + c) * D4_ + i] = run;

    // --- block 0 only: dtype detection over 1024 sampled entries -----------
    if (blk == 0) {
        unsigned int v = 0;
#pragma unroll
        for (int k = 0; k < 4; k++) v |= g32[2 * (k * 256 + i) + 1];
        sh[i] = v;
        __syncthreads();
        for (int o = 128; o > 0; o >>= 1) {
            if (i < o) sh[i] |= sh[i + o];
            __syncthreads();
        }
        if (i == 0) g_is32 = (sh[0] != 0u) ? 1 : 0;
    }
}

// ---------------------------------------------------------------------------
// 2) Hierarchical scan of 64 chunk totals: 512 blocks = b(8) x d-tile(64 of
//    16 d). Block: 16 d-lanes x 16 groups; each thread sums 4 chunks (MLP=4),
//    shared 16-way exclusive scan per d-lane, emits its 4 SP entries.
// ---------------------------------------------------------------------------
__global__ void __launch_bounds__(256) k_scan() {
    __shared__ float sh[16][16];
    int blk = blockIdx.x;               // 512 blocks
    int b = blk >> 6, dt = blk & 63;
    int dl = threadIdx.x & 15;          // d-lane within tile
    int gr = threadIdx.x >> 4;          // chunk group 0..15
    int d = dt * 16 + dl;

    const float* S = g_S + (size_t)b * NCH * D_ + d;
    float v[4];
#pragma unroll
    for (int j = 0; j < 4; j++) v[j] = S[(size_t)(gr * 4 + j) * D_];
    float gsum = (v[0] + v[1]) + (v[2] + v[3]);
    sh[gr][dl] = gsum;
    __syncthreads();

    float off = 0.f;
#pragma unroll
    for (int j = 0; j < 16; j++) { float t = sh[j][dl]; if (j < gr) off += t; }

    float* SPp = g_SP + (size_t)b * (NCH + 1) * D_ + d;
    float run = off;
#pragma unroll
    for (int j = 0; j < 4; j++) {
        SPp[(size_t)(gr * 4 + j) * D_] = run;
        run += v[j];
    }
    if (gr == 15) {
        SPp[(size_t)NCH * D_] = run;                              // SP[64] = total
        g_L[((size_t)b * (STEPS + 1) + STEPS) * D_ + d] = 0.f;    // L[q=STEPS] = 0
    }
}

// ---------------------------------------------------------------------------
// 3) Gather: per (b,t) block writes BOTH output rows.
//    pref(q) = SP[q>>4] + L[q].
//    seg  = (pref(qe)-pref(qs) +/- residual x rows) / len + EPS   -> out[2t]
//    win  = (pref(t+1) - pref(t)) / 3                             -> out[2t+1]
//    Ceiling trick for boundaries: k=3q+r: r==0 -> (q, none);
//    r==1 -> (q, +x[3q]); r==2 -> (q+1, -x[3q+2]).
// ---------------------------------------------------------------------------
__global__ void __launch_bounds__(256) k_gather(const float4* __restrict__ x,
                                                const void* __restrict__ graph,
                                                float4* __restrict__ out) {
    int bt = blockIdx.x;
    int b = bt >> 10, t = bt & 1023;
    int i = threadIdx.x;

    int s, e;
    if (g_is32) {
        int2 v = ((const int2*)graph)[bt];
        s = v.x; e = v.y;
    } else {
        longlong2 v = ((const longlong2*)graph)[bt];
        s = (int)v.x; e = (int)v.y;
    }
    int ke = e + 1, ks = s;
    int qe = ke / 3, re = ke - 3 * qe, resE = 0;       // end boundary (added)
    if (re == 1) resE = (3 * qe) + 1;                                  // + x[3q]
    else if (re == 2) { qe += 1; resE = -((3 * (qe - 1) + 2) + 1); }   // - x[3q+2]
    int qs = ks / 3, rs = ks - 3 * qs, resS = 0;       // start boundary (subtracted)
    if (rs == 1) resS = -((3 * qs) + 1);                               // - x[3q]
    else if (rs == 2) { qs += 1; resS = (3 * (qs - 1) + 2) + 1; }      // + x[3q+2]
    float invlen = 1.0f / (float)(ke - ks);

    const float4* L4  = (const float4*)g_L  + (size_t)b * (STEPS + 1) * D4_;
    const float4* SP4 = (const float4*)g_SP + (size_t)b * (NCH + 1) * D4_;
    const float4* x4  = x + (size_t)b * N_ * D4_;

    // all four prefix row loads issued independently (L2-hot)
    float4 Lqe = L4[(size_t)qe * D4_ + i];
    float4 Lqs = L4[(size_t)qs * D4_ + i];
    float4 Lt0 = L4[(size_t)t * D4_ + i];
    float4 Lt1 = L4[(size_t)(t + 1) * D4_ + i];
    float4 Sqe = SP4[(size_t)(qe >> 4) * D4_ + i];
    float4 Sqs = SP4[(size_t)(qs >> 4) * D4_ + i];
    float4 St0 = SP4[(size_t)(t >> 4) * D4_ + i];
    float4 St1 = SP4[(size_t)((t + 1) >> 4) * D4_ + i];

    float4 acc = f4sub(f4add(Lqe, Sqe), f4add(Lqs, Sqs));
    if (resE != 0) {
        int row = (resE > 0 ? resE : -resE) - 1;
        float sgn = (resE > 0) ? 1.f : -1.f;
        float4 v = ldcs4(&x4[(size_t)row * D4_ + i]);
        acc = make_float4(fmaf(sgn, v.x, acc.x), fmaf(sgn, v.y, acc.y),
                          fmaf(sgn, v.z, acc.z), fmaf(sgn, v.w, acc.w));
    }
    if (resS != 0) {
        int row = (resS > 0 ? resS : -resS) - 1;
        float sgn = (resS > 0) ? 1.f : -1.f;
        float4 v = ldcs4(&x4[(size_t)row * D4_ + i]);
        acc = make_float4(fmaf(sgn, v.x, acc.x), fmaf(sgn, v.y, acc.y),
                          fmaf(sgn, v.z, acc.z), fmaf(sgn, v.w, acc.w));
    }

    float4 segv = make_float4(acc.x * invlen + EPS_, acc.y * invlen + EPS_,
                              acc.z * invlen + EPS_, acc.w * invlen + EPS_);

    const float inv3 = 1.0f / 3.0f;
    float4 wdiff = f4sub(f4add(Lt1, St1), f4add(Lt0, St0));
    float4 winv = make_float4(wdiff.x * inv3, wdiff.y * inv3,
                              wdiff.z * inv3, wdiff.w * inv3);

    stcs4(&out[(size_t)(2 * bt) * D4_ + i], segv);
    stcs4(&out[(size_t)(2 * bt + 1) * D4_ + i], winv);
}

// ---------------------------------------------------------------------------
extern "C" void kernel_launch(void* const* d_in, const int* in_sizes, int n_in,
                              void* d_out, int out_size) {
    const float* x     = (const float*)d_in[0];
    const void*  graph = d_in[1];
    float*       out   = (float*)d_out;

    k_fused <<<B_ * NCH, 256>>>((const float4*)x, (const unsigned int*)graph,
                                (float4*)out);
    k_scan  <<<512, 256>>>();
    k_gather<<<B_ * STEPS, 256>>>((const float4*)x, graph, (float4*)out);
}

// round 14
// speedup vs baseline: 1.1264x; 1.1264x over previous
#include <cuda_runtime.h>

// Problem constants (fixed by setup_inputs)
#define B_     8
#define N_     3072
#define D_     1024
#define D4_    256          // D/4 (float4)
#define STEPS  1024         // N/POOL
#define POOL_  3
#define NCH    64           // chunks per batch
#define CWIN   16           // windows per chunk
#define EPS_   0.006f

// Scratch (__device__ globals; no allocations allowed)
__device__ float g_L [(size_t)B_ * (STEPS + 1) * D_];  // chunk-local exclusive window prefix
__device__ float g_S [(size_t)B_ * NCH * D_];          // chunk totals
__device__ float g_SP[(size_t)B_ * (NCH + 1) * D_];    // exclusive scan of chunk totals
__device__ int   g_is32;                               // 1 if graph is int32

__device__ __forceinline__ float4 f4add(float4 a, float4 b) {
    return make_float4(a.x + b.x, a.y + b.y, a.z + b.z, a.w + b.w);
}
__device__ __forceinline__ float4 f4sub(float4 a, float4 b) {
    return make_float4(a.x - b.x, a.y - b.y, a.z - b.z, a.w - b.w);
}
__device__ __forceinline__ float4 ldcs4(const float4* p) { return __ldcs(p); }
__device__ __forceinline__ void stcs4(float4* p, float4 v) { __stcs(p, v); }

// ---------------------------------------------------------------------------
// 1) Fused pass over x (streamed), depth-2 register pipeline. Writes ONLY the
//    chunk-local exclusive prefix L (L2-resident) and chunk totals S.
//    Block 0 also does graph-dtype detection.
// ---------------------------------------------------------------------------
__global__ void __launch_bounds__(256) k_fused(const float4* __restrict__ x,
                                               const unsigned int* __restrict__ g32) {
    __shared__ unsigned int sh[256];
    int blk = blockIdx.x;               // B*NCH = 512 blocks
    int b = blk >> 6, c = blk & 63;
    int q0 = c * CWIN;
    int i = threadIdx.x;

    const float4* xr = x + ((size_t)(b * N_ + POOL_ * q0)) * D4_ + i;
    float4* L4 = (float4*)g_L + ((size_t)b * (STEPS + 1) + q0) * D4_ + i;

    float4 run = make_float4(0.f, 0.f, 0.f, 0.f);

    // pipeline prologue: windows 0 and 1 in flight
    float4 A0 = ldcs4(&xr[0]);
    float4 B0 = ldcs4(&xr[(size_t)1 * D4_]);
    float4 C0 = ldcs4(&xr[(size_t)2 * D4_]);
    float4 A1 = ldcs4(&xr[(size_t)3 * D4_]);
    float4 B1 = ldcs4(&xr[(size_t)4 * D4_]);
    float4 C1 = ldcs4(&xr[(size_t)5 * D4_]);

#pragma unroll
    for (int w = 0; w < CWIN; w++) {
        float4 A2, B2, C2;
        if (w + 2 < CWIN) {                  // prefetch window w+2
            A2 = ldcs4(&xr[(size_t)(3 * (w + 2))     * D4_]);
            B2 = ldcs4(&xr[(size_t)(3 * (w + 2) + 1) * D4_]);
            C2 = ldcs4(&xr[(size_t)(3 * (w + 2) + 2) * D4_]);
        }
        L4[(size_t)w * D4_] = run;                       // keep in L2
        float4 sum = f4add(f4add(A0, B0), C0);           // raw row-sum
        run = f4add(run, sum);
        A0 = A1; B0 = B1; C0 = C1;
        A1 = A2; B1 = B2; C1 = C2;
    }
    ((float4*)g_S)[((size_t)b * NCH + c) * D4_ + i] = run;

    // --- block 0 only: dtype detection over 1024 sampled entries -----------
    if (blk == 0) {
        unsigned int v = 0;
#pragma unroll
        for (int k = 0; k < 4; k++) v |= g32[2 * (k * 256 + i) + 1];
        sh[i] = v;
        __syncthreads();
        for (int o = 128; o > 0; o >>= 1) {
            if (i < o) sh[i] |= sh[i + o];
            __syncthreads();
        }
        if (i == 0) g_is32 = (sh[0] != 0u) ? 1 : 0;
    }
}

// ---------------------------------------------------------------------------
// 1b) Win rows from chunk-local prefixes (depends ONLY on fused; runs on a
//     second stream overlapped with scan+gather):
//     winsum_t = (j<15 ? L[t+1] : S[c]) - L[t],  out[2t+1] = winsum/3.
// ---------------------------------------------------------------------------
__global__ void __launch_bounds__(256) k_win(float4* __restrict__ out) {
    int blk = blockIdx.x;               // 512 blocks = (b, chunk)
    int b = blk >> 6, c = blk & 63;
    int q0 = c * CWIN;
    int i = threadIdx.x;

    const float4* L4 = (const float4*)g_L + ((size_t)b * (STEPS + 1) + q0) * D4_ + i;
    float4 Sc = ((const float4*)g_S)[((size_t)b * NCH + c) * D4_ + i];
    float4* o4 = out + ((size_t)(b * 2 * STEPS) + 2 * q0 + 1) * D4_ + i;

    const float inv3 = 1.0f / 3.0f;
    float4 cur = L4[0];                                  // = 0 vector
#pragma unroll
    for (int j = 0; j < CWIN; j++) {
        float4 nxt = (j < CWIN - 1) ? L4[(size_t)(j + 1) * D4_] : Sc;
        float4 d = f4sub(nxt, cur);
        stcs4(&o4[(size_t)(2 * j) * D4_],
              make_float4(d.x * inv3, d.y * inv3, d.z * inv3, d.w * inv3));
        cur = nxt;
    }
}

// ---------------------------------------------------------------------------
// 2) Hierarchical scan of 64 chunk totals: 512 blocks = b(8) x d-tile(64 of
//    16 d). Block: 16 d-lanes x 16 groups; each thread sums 4 chunks (MLP=4),
//    shared 16-way exclusive scan per d-lane, emits its 4 SP entries.
// ---------------------------------------------------------------------------
__global__ void __launch_bounds__(256) k_scan() {
    __shared__ float sh[16][16];
    int blk = blockIdx.x;               // 512 blocks
    int b = blk >> 6, dt = blk & 63;
    int dl = threadIdx.x & 15;          // d-lane within tile
    int gr = threadIdx.x >> 4;          // chunk group 0..15
    int d = dt * 16 + dl;

    const float* S = g_S + (size_t)b * NCH * D_ + d;
    float v[4];
#pragma unroll
    for (int j = 0; j < 4; j++) v[j] = S[(size_t)(gr * 4 + j) * D_];
    float gsum = (v[0] + v[1]) + (v[2] + v[3]);
    sh[gr][dl] = gsum;
    __syncthreads();

    float off = 0.f;
#pragma unroll
    for (int j = 0; j < 16; j++) { float t = sh[j][dl]; if (j < gr) off += t; }

    float* SPp = g_SP + (size_t)b * (NCH + 1) * D_ + d;
    float run = off;
#pragma unroll
    for (int j = 0; j < 4; j++) {
        SPp[(size_t)(gr * 4 + j) * D_] = run;
        run += v[j];
    }
    if (gr == 15) {
        SPp[(size_t)NCH * D_] = run;                              // SP[64] = total
        g_L[((size_t)b * (STEPS + 1) + STEPS) * D_ + d] = 0.f;    // L[q=STEPS] = 0
    }
}

// ---------------------------------------------------------------------------
// 3) Gather (seg rows only, proven form): pref(q) = SP[q>>4] + L[q];
//    seg = (pref(qe)-pref(qs) +/- residual x rows)/len + EPS.
//    Ceiling trick: k=3q+r: r==0 -> (q,none); r==1 -> (q,+x[3q]);
//    r==2 -> (q+1,-x[3q+2]).
// ---------------------------------------------------------------------------
__global__ void __launch_bounds__(256) k_gather(const float4* __restrict__ x,
                                                const void* __restrict__ graph,
                                                float4* __restrict__ out) {
    int bt = blockIdx.x;
    int b = bt >> 10;
    int i = threadIdx.x;

    int s, e;
    if (g_is32) {
        int2 v = ((const int2*)graph)[bt];
        s = v.x; e = v.y;
    } else {
        longlong2 v = ((const longlong2*)graph)[bt];
        s = (int)v.x; e = (int)v.y;
    }
    int ke = e + 1, ks = s;
    int qe = ke / 3, re = ke - 3 * qe, resE = 0;       // end boundary (added)
    if (re == 1) resE = (3 * qe) + 1;                                  // + x[3q]
    else if (re == 2) { qe += 1; resE = -((3 * (qe - 1) + 2) + 1); }   // - x[3q+2]
    int qs = ks / 3, rs = ks - 3 * qs, resS = 0;       // start boundary (subtracted)
    if (rs == 1) resS = -((3 * qs) + 1);                               // - x[3q]
    else if (rs == 2) { qs += 1; resS = (3 * (qs - 1) + 2) + 1; }      // + x[3q+2]
    float invlen = 1.0f / (float)(ke - ks);

    const float4* L4  = (const float4*)g_L  + (size_t)b * (STEPS + 1) * D4_;
    const float4* SP4 = (const float4*)g_SP + (size_t)b * (NCH + 1) * D4_;
    const float4* x4  = x + (size_t)b * N_ * D4_;

    float4 pe = f4add(L4[(size_t)qe * D4_ + i], SP4[(size_t)(qe >> 4) * D4_ + i]);
    float4 ps = f4add(L4[(size_t)qs * D4_ + i], SP4[(size_t)(qs >> 4) * D4_ + i]);
    float4 acc = f4sub(pe, ps);

    if (resE != 0) {
        int row = (resE > 0 ? resE : -resE) - 1;
        float sgn = (resE > 0) ? 1.f : -1.f;
        float4 v = ldcs4(&x4[(size_t)row * D4_ + i]);
        acc = make_float4(fmaf(sgn, v.x, acc.x), fmaf(sgn, v.y, acc.y),
                          fmaf(sgn, v.z, acc.z), fmaf(sgn, v.w, acc.w));
    }
    if (resS != 0) {
        int row = (resS > 0 ? resS : -resS) - 1;
        float sgn = (resS > 0) ? 1.f : -1.f;
        float4 v = ldcs4(&x4[(size_t)row * D4_ + i]);
        acc = make_float4(fmaf(sgn, v.x, acc.x), fmaf(sgn, v.y, acc.y),
                          fmaf(sgn, v.z, acc.z), fmaf(sgn, v.w, acc.w));
    }

    float4 o = make_float4(acc.x * invlen + EPS_, acc.y * invlen + EPS_,
                           acc.z * invlen + EPS_, acc.w * invlen + EPS_);
    stcs4(&out[(size_t)(2 * bt) * D4_ + i], o);
}

// ---------------------------------------------------------------------------
// Launch: fork k_win onto a second stream after k_fused; scan+gather stay on
// the main stream; join before returning. Streams/events are created lazily
// on the (un-captured) correctness call; record/wait during capture become
// graph edges.
// ---------------------------------------------------------------------------
extern "C" void kernel_launch(void* const* d_in, const int* in_sizes, int n_in,
                              void* d_out, int out_size) {
    const float* x     = (const float*)d_in[0];
    const void*  graph = d_in[1];
    float*       out   = (float*)d_out;

    static cudaStream_t s2 = nullptr;
    static cudaEvent_t evFork = nullptr, evJoin = nullptr;
    if (s2 == nullptr) {
        cudaStreamCreateWithFlags(&s2, cudaStreamNonBlocking);
        cudaEventCreateWithFlags(&evFork, cudaEventDisableTiming);
        cudaEventCreateWithFlags(&evJoin, cudaEventDisableTiming);
    }

    k_fused<<<B_ * NCH, 256>>>((const float4*)x, (const unsigned int*)graph);

    cudaEventRecord(evFork, 0);                 // fork point after fused
    cudaStreamWaitEvent(s2, evFork, 0);
    k_win   <<<B_ * NCH, 256, 0, s2>>>((float4*)out);     // overlapped branch

    k_scan  <<<512, 256>>>();
    k_gather<<<B_ * STEPS, 256>>>((const float4*)x, graph, (float4*)out);

    cudaEventRecord(evJoin, s2);                // join back to main stream
    cudaStreamWaitEvent(0, evJoin, 0);
}

// round 15
// speedup vs baseline: 1.1371x; 1.0095x over previous
#include <cuda_runtime.h>

// Problem constants (fixed by setup_inputs)
#define B_     8
#define N_     3072
#define D_     1024
#define D4_    256          // D/4 (float4)
#define STEPS  1024         // N/POOL
#define POOL_  3
#define NCH    64           // chunks per batch
#define CWIN   16           // windows per chunk
#define EPS_   0.006f

// Scratch (__device__ globals; no allocations allowed)
__device__ float g_L [(size_t)B_ * (STEPS + 1) * D_];  // chunk-local exclusive window prefix
__device__ float g_S [(size_t)B_ * NCH * D_];          // chunk totals
__device__ float g_SP[(size_t)B_ * (NCH + 1) * D_];    // exclusive scan of chunk totals
__device__ int   g_is32;                               // 1 if graph is int32

__device__ __forceinline__ float4 f4add(float4 a, float4 b) {
    return make_float4(a.x + b.x, a.y + b.y, a.z + b.z, a.w + b.w);
}
__device__ __forceinline__ float4 f4sub(float4 a, float4 b) {
    return make_float4(a.x - b.x, a.y - b.y, a.z - b.z, a.w - b.w);
}
__device__ __forceinline__ float4 ldcs4(const float4* p) { return __ldcs(p); }
__device__ __forceinline__ void stcs4(float4* p, float4 v) { __stcs(p, v); }

// ---------------------------------------------------------------------------
// 1) Fused pass over x (streamed), depth-2 register pipeline. Writes ONLY the
//    chunk-local exclusive prefix L (L2-resident) and chunk totals S.
//    Block 0 also does graph-dtype detection.
// ---------------------------------------------------------------------------
__global__ void __launch_bounds__(256) k_fused(const float4* __restrict__ x,
                                               const unsigned int* __restrict__ g32) {
    __shared__ unsigned int sh[256];
    int blk = blockIdx.x;               // B*NCH = 512 blocks
    int b = blk >> 6, c = blk & 63;
    int q0 = c * CWIN;
    int i = threadIdx.x;

    const float4* xr = x + ((size_t)(b * N_ + POOL_ * q0)) * D4_ + i;
    float4* L4 = (float4*)g_L + ((size_t)b * (STEPS + 1) + q0) * D4_ + i;

    float4 run = make_float4(0.f, 0.f, 0.f, 0.f);

    // pipeline prologue: windows 0 and 1 in flight
    float4 A0 = ldcs4(&xr[0]);
    float4 B0 = ldcs4(&xr[(size_t)1 * D4_]);
    float4 C0 = ldcs4(&xr[(size_t)2 * D4_]);
    float4 A1 = ldcs4(&xr[(size_t)3 * D4_]);
    float4 B1 = ldcs4(&xr[(size_t)4 * D4_]);
    float4 C1 = ldcs4(&xr[(size_t)5 * D4_]);

#pragma unroll
    for (int w = 0; w < CWIN; w++) {
        float4 A2, B2, C2;
        if (w + 2 < CWIN) {                  // prefetch window w+2
            A2 = ldcs4(&xr[(size_t)(3 * (w + 2))     * D4_]);
            B2 = ldcs4(&xr[(size_t)(3 * (w + 2) + 1) * D4_]);
            C2 = ldcs4(&xr[(size_t)(3 * (w + 2) + 2) * D4_]);
        }
        L4[(size_t)w * D4_] = run;                       // keep in L2
        float4 sum = f4add(f4add(A0, B0), C0);           // raw row-sum
        run = f4add(run, sum);
        A0 = A1; B0 = B1; C0 = C1;
        A1 = A2; B1 = B2; C1 = C2;
    }
    ((float4*)g_S)[((size_t)b * NCH + c) * D4_ + i] = run;

    // --- block 0 only: dtype detection over 1024 sampled entries -----------
    if (blk == 0) {
        unsigned int v = 0;
#pragma unroll
        for (int k = 0; k < 4; k++) v |= g32[2 * (k * 256 + i) + 1];
        sh[i] = v;
        __syncthreads();
        for (int o = 128; o > 0; o >>= 1) {
            if (i < o) sh[i] |= sh[i + o];
            __syncthreads();
        }
        if (i == 0) g_is32 = (sh[0] != 0u) ? 1 : 0;
    }
}

// ---------------------------------------------------------------------------
// 1b) Win rows from chunk-local prefixes (depends ONLY on fused; runs on a
//     second stream overlapped with scan+gather):
//     winsum_t = (j<15 ? L[t+1] : S[c]) - L[t],  out[2t+1] = winsum/3.
// ---------------------------------------------------------------------------
__global__ void __launch_bounds__(256) k_win(float4* __restrict__ out) {
    int blk = blockIdx.x;               // 512 blocks = (b, chunk)
    int b = blk >> 6, c = blk & 63;
    int q0 = c * CWIN;
    int i = threadIdx.x;

    const float4* L4 = (const float4*)g_L + ((size_t)b * (STEPS + 1) + q0) * D4_ + i;
    float4 Sc = ((const float4*)g_S)[((size_t)b * NCH + c) * D4_ + i];
    float4* o4 = out + ((size_t)(b * 2 * STEPS) + 2 * q0 + 1) * D4_ + i;

    const float inv3 = 1.0f / 3.0f;
    float4 cur = L4[0];                                  // = 0 vector
#pragma unroll
    for (int j = 0; j < CWIN; j++) {
        float4 nxt = (j < CWIN - 1) ? L4[(size_t)(j + 1) * D4_] : Sc;
        float4 d = f4sub(nxt, cur);
        stcs4(&o4[(size_t)(2 * j) * D4_],
              make_float4(d.x * inv3, d.y * inv3, d.z * inv3, d.w * inv3));
        cur = nxt;
    }
}

// ---------------------------------------------------------------------------
// 2) Hierarchical scan of 64 chunk totals: 512 blocks = b(8) x d-tile(64 of
//    16 d). Block: 16 d-lanes x 16 groups; each thread sums 4 chunks (MLP=4),
//    shared 16-way exclusive scan per d-lane, emits its 4 SP entries.
// ---------------------------------------------------------------------------
__global__ void __launch_bounds__(256) k_scan() {
    __shared__ float sh[16][16];
    int blk = blockIdx.x;               // 512 blocks
    int b = blk >> 6, dt = blk & 63;
    int dl = threadIdx.x & 15;          // d-lane within tile
    int gr = threadIdx.x >> 4;          // chunk group 0..15
    int d = dt * 16 + dl;

    const float* S = g_S + (size_t)b * NCH * D_ + d;
    float v[4];
#pragma unroll
    for (int j = 0; j < 4; j++) v[j] = S[(size_t)(gr * 4 + j) * D_];
    float gsum = (v[0] + v[1]) + (v[2] + v[3]);
    sh[gr][dl] = gsum;
    __syncthreads();

    float off = 0.f;
#pragma unroll
    for (int j = 0; j < 16; j++) { float t = sh[j][dl]; if (j < gr) off += t; }

    float* SPp = g_SP + (size_t)b * (NCH + 1) * D_ + d;
    float run = off;
#pragma unroll
    for (int j = 0; j < 4; j++) {
        SPp[(size_t)(gr * 4 + j) * D_] = run;
        run += v[j];
    }
    if (gr == 15) {
        SPp[(size_t)NCH * D_] = run;                              // SP[64] = total
        g_L[((size_t)b * (STEPS + 1) + STEPS) * D_ + d] = 0.f;    // L[q=STEPS] = 0
    }
}

// ---------------------------------------------------------------------------
// 3) Gather, 2 SEGMENTS PER BLOCK for doubled MLP: grid 4096 = b(8) x 512
//    pairs. All 8 prefix loads + residuals issued independently, then both
//    seg rows computed and stored.
//    pref(q) = SP[q>>4] + L[q]; ceiling trick for boundaries.
// ---------------------------------------------------------------------------
__device__ __forceinline__ void seg_idx(int s, int e, int& qe, int& resE,
                                        int& qs, int& resS, float& invlen) {
    int ke = e + 1, ks = s;
    qe = ke / 3; int re = ke - 3 * qe; resE = 0;
    if (re == 1) resE = (3 * qe) + 1;                                  // + x[3q]
    else if (re == 2) { qe += 1; resE = -((3 * (qe - 1) + 2) + 1); }   // - x[3q+2]
    qs = ks / 3; int rs = ks - 3 * qs; resS = 0;
    if (rs == 1) resS = -((3 * qs) + 1);                               // - x[3q]
    else if (rs == 2) { qs += 1; resS = (3 * (qs - 1) + 2) + 1; }      // + x[3q+2]
    invlen = 1.0f / (float)(ke - ks);
}

__global__ void __launch_bounds__(256) k_gather(const float4* __restrict__ x,
                                                const void* __restrict__ graph,
                                                float4* __restrict__ out) {
    int blk = blockIdx.x;               // 4096 blocks
    int b = blk >> 9, tp = blk & 511;
    int bt0 = (b << 10) + 2 * tp;       // segment indices bt0, bt0+1
    int i = threadIdx.x;

    int s0, e0, s1, e1;
    if (g_is32) {
        int2 v0 = ((const int2*)graph)[bt0];
        int2 v1 = ((const int2*)graph)[bt0 + 1];
        s0 = v0.x; e0 = v0.y; s1 = v1.x; e1 = v1.y;
    } else {
        longlong2 v0 = ((const longlong2*)graph)[bt0];
        longlong2 v1 = ((const longlong2*)graph)[bt0 + 1];
        s0 = (int)v0.x; e0 = (int)v0.y; s1 = (int)v1.x; e1 = (int)v1.y;
    }
    int qe0, resE0, qs0, resS0, qe1, resE1, qs1, resS1;
    float inv0, inv1;
    seg_idx(s0, e0, qe0, resE0, qs0, resS0, inv0);
    seg_idx(s1, e1, qe1, resE1, qs1, resS1, inv1);

    const float4* L4  = (const float4*)g_L  + (size_t)b * (STEPS + 1) * D4_;
    const float4* SP4 = (const float4*)g_SP + (size_t)b * (NCH + 1) * D4_;
    const float4* x4  = x + (size_t)b * N_ * D4_;

    // 8 independent prefix loads in flight
    float4 Le0 = L4[(size_t)qe0 * D4_ + i];
    float4 Ls0 = L4[(size_t)qs0 * D4_ + i];
    float4 Le1 = L4[(size_t)qe1 * D4_ + i];
    float4 Ls1 = L4[(size_t)qs1 * D4_ + i];
    float4 Pe0 = SP4[(size_t)(qe0 >> 4) * D4_ + i];
    float4 Ps0 = SP4[(size_t)(qs0 >> 4) * D4_ + i];
    float4 Pe1 = SP4[(size_t)(qe1 >> 4) * D4_ + i];
    float4 Ps1 = SP4[(size_t)(qs1 >> 4) * D4_ + i];

    float4 acc0 = f4sub(f4add(Le0, Pe0), f4add(Ls0, Ps0));
    float4 acc1 = f4sub(f4add(Le1, Pe1), f4add(Ls1, Ps1));

#pragma unroll
    for (int k = 0; k < 2; k++) {
        int res = k == 0 ? (k ? 0 : resE0) : 0; // placeholder (unrolled below)
    }
    // residuals (up to 4, independent)
    if (resE0 != 0) {
        int row = (resE0 > 0 ? resE0 : -resE0) - 1;
        float sgn = (resE0 > 0) ? 1.f : -1.f;
        float4 v = ldcs4(&x4[(size_t)row * D4_ + i]);
        acc0 = make_float4(fmaf(sgn, v.x, acc0.x), fmaf(sgn, v.y, acc0.y),
                           fmaf(sgn, v.z, acc0.z), fmaf(sgn, v.w, acc0.w));
    }
    if (resS0 != 0) {
        int row = (resS0 > 0 ? resS0 : -resS0) - 1;
        float sgn = (resS0 > 0) ? 1.f : -1.f;
        float4 v = ldcs4(&x4[(size_t)row * D4_ + i]);
        acc0 = make_float4(fmaf(sgn, v.x, acc0.x), fmaf(sgn, v.y, acc0.y),
                           fmaf(sgn, v.z, acc0.z), fmaf(sgn, v.w, acc0.w));
    }
    if (resE1 != 0) {
        int row = (resE1 > 0 ? resE1 : -resE1) - 1;
        float sgn = (resE1 > 0) ? 1.f : -1.f;
        float4 v = ldcs4(&x4[(size_t)row * D4_ + i]);
        acc1 = make_float4(fmaf(sgn, v.x, acc1.x), fmaf(sgn, v.y, acc1.y),
                           fmaf(sgn, v.z, acc1.z), fmaf(sgn, v.w, acc1.w));
    }
    if (resS1 != 0) {
        int row = (resS1 > 0 ? resS1 : -resS1) - 1;
        float sgn = (resS1 > 0) ? 1.f : -1.f;
        float4 v = ldcs4(&x4[(size_t)row * D4_ + i]);
        acc1 = make_float4(fmaf(sgn, v.x, acc1.x), fmaf(sgn, v.y, acc1.y),
                           fmaf(sgn, v.z, acc1.z), fmaf(sgn, v.w, acc1.w));
    }

    float4 o0 = make_float4(acc0.x * inv0 + EPS_, acc0.y * inv0 + EPS_,
                            acc0.z * inv0 + EPS_, acc0.w * inv0 + EPS_);
    float4 o1 = make_float4(acc1.x * inv1 + EPS_, acc1.y * inv1 + EPS_,
                            acc1.z * inv1 + EPS_, acc1.w * inv1 + EPS_);
    stcs4(&out[(size_t)(2 * bt0) * D4_ + i], o0);
    stcs4(&out[(size_t)(2 * bt0 + 2) * D4_ + i], o1);
}

// ---------------------------------------------------------------------------
// Launch: fork k_win onto a second stream after k_fused; scan+gather stay on
// the main stream; join before returning.
// ---------------------------------------------------------------------------
extern "C" void kernel_launch(void* const* d_in, const int* in_sizes, int n_in,
                              void* d_out, int out_size) {
    const float* x     = (const float*)d_in[0];
    const void*  graph = d_in[1];
    float*       out   = (float*)d_out;

    static cudaStream_t s2 = nullptr;
    static cudaEvent_t evFork = nullptr, evJoin = nullptr;
    if (s2 == nullptr) {
        cudaStreamCreateWithFlags(&s2, cudaStreamNonBlocking);
        cudaEventCreateWithFlags(&evFork, cudaEventDisableTiming);
        cudaEventCreateWithFlags(&evJoin, cudaEventDisableTiming);
    }

    k_fused<<<B_ * NCH, 256>>>((const float4*)x, (const unsigned int*)graph);

    cudaEventRecord(evFork, 0);                 // fork point after fused
    cudaStreamWaitEvent(s2, evFork, 0);
    k_win   <<<B_ * NCH, 256, 0, s2>>>((float4*)out);     // overlapped branch

    k_scan  <<<512, 256>>>();
    k_gather<<<B_ * STEPS / 2, 256>>>((const float4*)x, graph, (float4*)out);

    cudaEventRecord(evJoin, s2);                // join back to main stream
    cudaStreamWaitEvent(0, evJoin, 0);
}